// round 11
// baseline (speedup 1.0000x reference)
#include <cuda_runtime.h>
#include <cuda_bf16.h>
#include <cstdint>

// B=32, P=64, D=34, L=1048576
// inputs: preds [B, L] f32, gts [B, P, D, 3] f32   output: [B] f32
// out[b] = sum_{valid} |preds[b, idx] - val| / #persons-with-any-valid-dim
//
// Two-kernel graph: (1) wide tail-free gather kernel writes per-CTA partials
// with plain stores; (2) tiny combine kernel. The kernel boundary provides
// all cross-CTA ordering -> zero gpu-scope fences/atomics anywhere.

#define RB   32
#define RP   64
#define RD   34
#define RL   1048576
#define NPD  (RP * RD)            // 2176 entries per batch
#define CPB  4                    // CTAs per batch
#define NCTA (RB * CPB)           // 128 CTAs, single wave
#define EPC  (NPD / CPB)          // 544 entries = exactly 16 whole persons
#define PPC  (RP / CPB)           // 16 persons per CTA
#define NT1  512                  // threads in kernel1
#define NW1  (NT1 / 32)           // 16 warps

// Per-CTA partials; fully overwritten by kernel1 every launch (replay-safe).
__device__ float p_sum[NCTA];
__device__ float p_np[NCTA];

__global__ __launch_bounds__(NT1, 2)
void regl1_partial(const float* __restrict__ preds,
                   const float* __restrict__ gts)
{
    const int cta  = blockIdx.x;
    const int b    = cta >> 2;            // batch
    const int c    = cta & 3;             // quarter
    const int tid  = threadIdx.x;
    const int warp = tid >> 5;
    const int lane = tid & 31;
    const int base = c * EPC;

    __shared__ float s_any[PPC];
    __shared__ float s_wsum[NW1];

    if (tid < PPC) s_any[tid] = 0.0f;
    __syncthreads();

    const float* __restrict__ g  = gts   + (size_t)b * NPD * 3;
    const float* __restrict__ pr = preds + (size_t)b * RL;

    // e0: all 512 threads.  e1: 32 leftovers = 2 lanes per warp (16 warps).
    const int  e0   = base + tid;
    const bool has1 = (lane < 2);
    const int  e1   = base + NT1 + (warp << 1) + lane;   // valid when has1

    // Independent gts loads first (max MLP), then gathers ASAP.
    const float val0 = g[e0 * 3 + 0];
    const unsigned i0 = (unsigned)(int)g[e0 * 3 + 1];
    const float flg0 = g[e0 * 3 + 2];

    const int  e1s  = has1 ? e1 : base;                  // in-bounds dummy
    const float val1 = g[e1s * 3 + 0];
    const unsigned i1 = (unsigned)(int)g[e1s * 3 + 1];
    const float flg1 = has1 ? g[e1s * 3 + 2] : -1.0f;

    const float gat0 = __ldg(pr + i0);                   // idx in [0,L) by setup
    const float gat1 = __ldg(pr + i1);

    float sum = 0.0f;
    if (flg0 > 0.0f) { sum += fabsf(gat0 - val0); s_any[(e0 - base) / RD] = 1.0f; }
    if (flg1 > 0.0f) { sum += fabsf(gat1 - val1); s_any[(e1 - base) / RD] = 1.0f; }

    #pragma unroll
    for (int off = 16; off > 0; off >>= 1)
        sum += __shfl_down_sync(0xFFFFFFFFu, sum, off);
    if (lane == 0) s_wsum[warp] = sum;
    __syncthreads();

    if (warp == 0) {
        float tot = (lane < NW1) ? s_wsum[lane] : 0.0f;
        #pragma unroll
        for (int off = 8; off > 0; off >>= 1)
            tot += __shfl_down_sync(0xFFFFFFFFu, tot, off);

        float np = (lane < PPC) ? s_any[lane] : 0.0f;
        #pragma unroll
        for (int off = 8; off > 0; off >>= 1)
            np += __shfl_down_sync(0xFFFFFFFFu, np, off);

        if (lane == 0) { p_sum[cta] = tot; p_np[cta] = np; }
    }
}

__global__ __launch_bounds__(NCTA, 1)
void regl1_combine(float* __restrict__ out)
{
    const int tid = threadIdx.x;      // 0..127
    float s = p_sum[tid];
    float n = p_np[tid];
    // segmented 4-lane reduction (CTAs of one batch are adjacent)
    s += __shfl_down_sync(0xFFFFFFFFu, s, 1, 4);
    s += __shfl_down_sync(0xFFFFFFFFu, s, 2, 4);
    n += __shfl_down_sync(0xFFFFFFFFu, n, 1, 4);
    n += __shfl_down_sync(0xFFFFFFFFu, n, 2, 4);
    if ((tid & 3) == 0)
        out[tid >> 2] = s / n;        // reference guarantees n >= 1
}

extern "C" void kernel_launch(void* const* d_in, const int* in_sizes, int n_in,
                              void* d_out, int out_size)
{
    const float* preds = (const float*)d_in[0];
    const float* gts   = (const float*)d_in[1];
    float* out         = (float*)d_out;
    regl1_partial<<<NCTA, NT1>>>(preds, gts);
    regl1_combine<<<1, NCTA>>>(out);
}

// round 12
// speedup vs baseline: 1.1878x; 1.1878x over previous
#include <cuda_runtime.h>
#include <cuda_bf16.h>
#include <cstdint>

// B=32, P=64, D=34, L=1048576
// inputs: preds [B, L] f32, gts [B, P, D, 3] f32   output: [B] f32
// out[b] = sum_{valid} |preds[b, idx] - val| / #persons-with-any-valid-dim
//
// Single kernel, 32 CTAs x 1024 threads. Warp-local everything:
// warp w owns entries [68w, 68w+68) = exactly persons {2w, 2w+1}.
//  - float4 gts staging through smem (warp-private segment, __syncwarp only)
//  - num_people via ballots (no shared flag array, no opening __syncthreads)
//  - one block sync total, then warp0 reduces 32 float2 partials.

#define RB   32
#define RP   64
#define RD   34
#define RL   1048576
#define NPD  (RP * RD)            // 2176 entries per batch
#define NTHREADS 1024
#define NWARPS  (NTHREADS / 32)   // 32
#define EPW  68                   // entries per warp (= 2 persons)
#define F4W  51                   // float4s per warp (68*3/4)

__global__ __launch_bounds__(NTHREADS, 1)
void regl1_kernel(const float* __restrict__ preds,
                  const float* __restrict__ gts,
                  float* __restrict__ out)
{
    const int b    = blockIdx.x;
    const int tid  = threadIdx.x;
    const int warp = tid >> 5;
    const int lane = tid & 31;

    __shared__ float4 sg4[NWARPS * F4W];   // 26112 B staged gts
    __shared__ float2 s_part[NWARPS];      // {sum, np} per warp

    // --- stage this warp's gts segment with vector loads (no block sync) ---
    const float4* __restrict__ g4 =
        (const float4*)(gts + (size_t)b * NPD * 3) + warp * F4W;
    float4* my4 = sg4 + warp * F4W;

    my4[lane] = g4[lane];                      // 32 x 16B
    if (lane < F4W - 32)                       // 19 x 16B
        my4[lane + 32] = g4[lane + 32];
    __syncwarp();

    const float* sg = (const float*)my4;       // 204 floats: 68 triples
    const float* __restrict__ pr = preds + (size_t)b * RL;

    // entries handled by this lane: e0 = lane, e1 = lane+32, e2 = lane+64 (lane<4)
    const bool has2 = (lane < EPW - 64);

    // idx first (stride-3 LDS: conflict-free), gathers ASAP
    const unsigned i0 = (unsigned)(int)sg[3 * lane + 1];
    const unsigned i1 = (unsigned)(int)sg[3 * (lane + 32) + 1];
    const unsigned i2 = has2 ? (unsigned)(int)sg[3 * (lane + 64) + 1] : 0u;

    const float gat0 = __ldg(pr + i0);         // idx in [0,L) by setup
    const float gat1 = __ldg(pr + i1);
    const float gat2 = __ldg(pr + i2);

    const float val0 = sg[3 * lane + 0],        flg0 = sg[3 * lane + 2];
    const float val1 = sg[3 * (lane + 32) + 0], flg1 = sg[3 * (lane + 32) + 2];
    const float val2 = has2 ? sg[3 * (lane + 64) + 0] : 0.0f;
    const float flg2 = has2 ? sg[3 * (lane + 64) + 2] : -1.0f;

    const bool v0 = (flg0 > 0.0f);
    const bool v1 = (flg1 > 0.0f);
    const bool v2 = (flg2 > 0.0f);

    float sum = 0.0f;
    if (v0) sum += fabsf(gat0 - val0);
    if (v1) sum += fabsf(gat1 - val1);
    if (v2) sum += fabsf(gat2 - val2);

    // person A = entries 0..33 (e0 all lanes; e1 lanes 0,1)
    // person B = entries 34..67 (e1 lanes 2..31; e2 lanes 0..3)
    const unsigned b0 = __ballot_sync(0xFFFFFFFFu, v0);
    const unsigned b1 = __ballot_sync(0xFFFFFFFFu, v1);
    const unsigned b2 = __ballot_sync(0xFFFFFFFFu, v2);
    const float np = (float)(((b0 | (b1 & 0x3u)) != 0u) +
                             (((b1 & ~0x3u) | b2) != 0u));

    #pragma unroll
    for (int off = 16; off > 0; off >>= 1)
        sum += __shfl_down_sync(0xFFFFFFFFu, sum, off);
    if (lane == 0) s_part[warp] = make_float2(sum, np);
    __syncthreads();

    if (warp == 0) {
        float2 v = s_part[lane];               // 32 warps
        #pragma unroll
        for (int off = 16; off > 0; off >>= 1) {
            v.x += __shfl_down_sync(0xFFFFFFFFu, v.x, off);
            v.y += __shfl_down_sync(0xFFFFFFFFu, v.y, off);
        }
        if (lane == 0)
            out[b] = v.x / v.y;                // reference guarantees np >= 1
    }
}

extern "C" void kernel_launch(void* const* d_in, const int* in_sizes, int n_in,
                              void* d_out, int out_size)
{
    const float* preds = (const float*)d_in[0];
    const float* gts   = (const float*)d_in[1];
    float* out         = (float*)d_out;
    regl1_kernel<<<RB, NTHREADS>>>(preds, gts, out);
}

// round 13
// speedup vs baseline: 1.2593x; 1.0602x over previous
#include <cuda_runtime.h>
#include <cuda_bf16.h>
#include <cstdint>

// B=32, P=64, D=34, L=1048576
// inputs: preds [B, L] f32, gts [B, P, D, 3] f32   output: [B] f32
// out[b] = sum_{valid} |preds[b, idx] - val| / #persons-with-any-valid-dim
//
// grid=128 as 32 clusters of 4 CTAs (one cluster per batch). Each CTA gathers
// its quarter (544 entries = 16 whole persons) and the cluster combines via
// DSMEM: barrier.cluster (release/acquire, ~380cyc) + 3 remote smem reads.
// No gpu-scope atomics, no second kernel.

#define RB   32
#define RP   64
#define RD   34
#define RL   1048576
#define NPD  (RP * RD)            // 2176 entries per batch
#define CPB  4                    // CTAs (cluster size) per batch
#define NCTA (RB * CPB)           // 128
#define EPC  (NPD / CPB)          // 544 entries = exactly 16 whole persons
#define PPC  (RP / CPB)           // 16 persons per CTA
#define NT   512
#define NW   (NT / 32)            // 16 warps

__global__ __launch_bounds__(NT, 1) __cluster_dims__(CPB, 1, 1)
void regl1_kernel(const float* __restrict__ preds,
                  const float* __restrict__ gts,
                  float* __restrict__ out)
{
    const int b    = blockIdx.x >> 2;       // batch  (cluster id)
    const int rank = blockIdx.x & 3;        // cluster_ctarank (1-D cluster)
    const int tid  = threadIdx.x;
    const int warp = tid >> 5;
    const int lane = tid & 31;
    const int base = rank * EPC;

    __shared__ float s_any[PPC];
    __shared__ float s_wsum[NW];
    __shared__ float2 s_cta;                // this CTA's {sum, np} partial

    if (tid < PPC) s_any[tid] = 0.0f;
    __syncthreads();

    const float* __restrict__ g  = gts   + (size_t)b * NPD * 3;
    const float* __restrict__ pr = preds + (size_t)b * RL;

    // e0: all 512 threads.  e1: 32 leftovers = 2 lanes per warp.
    const int  e0   = base + tid;
    const bool has1 = (lane < 2);
    const int  e1   = base + NT + (warp << 1) + lane;    // valid when has1

    const float val0 = g[e0 * 3 + 0];
    const unsigned i0 = (unsigned)(int)g[e0 * 3 + 1];
    const float flg0 = g[e0 * 3 + 2];

    const int  e1s  = has1 ? e1 : base;                  // in-bounds dummy
    const float val1 = g[e1s * 3 + 0];
    const unsigned i1 = (unsigned)(int)g[e1s * 3 + 1];
    const float flg1 = has1 ? g[e1s * 3 + 2] : -1.0f;

    const float gat0 = __ldg(pr + i0);                   // idx in [0,L) by setup
    const float gat1 = __ldg(pr + i1);

    float sum = 0.0f;
    if (flg0 > 0.0f) { sum += fabsf(gat0 - val0); s_any[(e0 - base) / RD] = 1.0f; }
    if (flg1 > 0.0f) { sum += fabsf(gat1 - val1); s_any[(e1 - base) / RD] = 1.0f; }

    #pragma unroll
    for (int off = 16; off > 0; off >>= 1)
        sum += __shfl_down_sync(0xFFFFFFFFu, sum, off);
    if (lane == 0) s_wsum[warp] = sum;
    __syncthreads();

    if (warp == 0) {
        float tot = (lane < NW) ? s_wsum[lane] : 0.0f;
        #pragma unroll
        for (int off = 8; off > 0; off >>= 1)
            tot += __shfl_down_sync(0xFFFFFFFFu, tot, off);

        float np = (lane < PPC) ? s_any[lane] : 0.0f;
        #pragma unroll
        for (int off = 8; off > 0; off >>= 1)
            np += __shfl_down_sync(0xFFFFFFFFu, np, off);

        if (lane == 0) s_cta = make_float2(tot, np);
    }

    // cluster combine: arrive = release (orders s_cta store), wait = acquire
    asm volatile("barrier.cluster.arrive.aligned;" ::: "memory");
    asm volatile("barrier.cluster.wait.aligned;"   ::: "memory");

    if (rank == 0 && tid == 0) {
        float s = s_cta.x, n = s_cta.y;
        uint32_t laddr;
        asm("{ .reg .u64 t; cvta.to.shared.u64 t, %1; cvt.u32.u64 %0, t; }"
            : "=r"(laddr) : "l"((const void*)&s_cta));
        #pragma unroll
        for (int r = 1; r < CPB; ++r) {
            uint32_t raddr; float px, py;
            asm("mapa.shared::cluster.u32 %0, %1, %2;"
                : "=r"(raddr) : "r"(laddr), "r"(r));
            asm volatile("ld.shared::cluster.v2.f32 {%0, %1}, [%2];"
                         : "=f"(px), "=f"(py) : "r"(raddr));
            s += px; n += py;
        }
        out[b] = s / n;            // reference guarantees n >= 1
    }

    // keep peer smem alive until rank0 finished reading
    asm volatile("barrier.cluster.arrive.aligned;" ::: "memory");
    asm volatile("barrier.cluster.wait.aligned;"   ::: "memory");
}

extern "C" void kernel_launch(void* const* d_in, const int* in_sizes, int n_in,
                              void* d_out, int out_size)
{
    const float* preds = (const float*)d_in[0];
    const float* gts   = (const float*)d_in[1];
    float* out         = (float*)d_out;
    regl1_kernel<<<NCTA, NT>>>(preds, gts, out);
}

// round 14
// speedup vs baseline: 1.3140x; 1.0435x over previous
#include <cuda_runtime.h>
#include <cuda_bf16.h>
#include <cstdint>

// B=32, P=64, D=34, L=1048576
// inputs: preds [B, L] f32, gts [B, P, D, 3] f32   output: [B] f32
// out[b] = sum_{valid} |preds[b, idx] - val| / #persons-with-any-valid-dim
//
// Single kernel, 32 CTAs x 1024 threads — minimal critical path:
//  - warp w owns entries [68w, 68w+68) = exactly persons {2w, 2w+1}
//  - direct scalar gts loads (no staging), gathers issue ASAP
//  - num_people via ballots (no shared flag array, no opening barrier)
//  - exactly one __syncthreads; warp0 reduces 32 float2 partials.

#define RB   32
#define RP   64
#define RD   34
#define RL   1048576
#define NPD  (RP * RD)            // 2176 entries per batch
#define NTHREADS 1024
#define NWARPS  (NTHREADS / 32)   // 32
#define EPW  68                   // entries per warp (= 2 whole persons)

__global__ __launch_bounds__(NTHREADS, 1)
void regl1_kernel(const float* __restrict__ preds,
                  const float* __restrict__ gts,
                  float* __restrict__ out)
{
    const int b    = blockIdx.x;
    const int tid  = threadIdx.x;
    const int warp = tid >> 5;
    const int lane = tid & 31;

    __shared__ float2 s_part[NWARPS];      // {sum, np} per warp

    const float* __restrict__ g  = gts + (size_t)b * NPD * 3 + (size_t)warp * EPW * 3;
    const float* __restrict__ pr = preds + (size_t)b * RL;

    // lane handles e0 = lane, e1 = lane+32, e2 = lane+64 (lane < 4) within segment
    const bool has2 = (lane < EPW - 64);
    const int  o0 = 3 * lane;
    const int  o1 = 3 * (lane + 32);
    const int  o2 = has2 ? 3 * (lane + 64) : 0;    // in-bounds dummy

    // independent gts loads first, idx before val/flg so gathers issue ASAP
    const unsigned i0 = (unsigned)(int)g[o0 + 1];
    const unsigned i1 = (unsigned)(int)g[o1 + 1];
    const unsigned i2 = (unsigned)(int)g[o2 + 1];

    const float gat0 = __ldg(pr + i0);             // idx in [0,L) by setup
    const float gat1 = __ldg(pr + i1);
    const float gat2 = __ldg(pr + i2);

    const float val0 = g[o0 + 0], flg0 = g[o0 + 2];
    const float val1 = g[o1 + 0], flg1 = g[o1 + 2];
    const float val2 = g[o2 + 0];
    const float flg2 = has2 ? g[o2 + 2] : -1.0f;

    const bool v0 = (flg0 > 0.0f);
    const bool v1 = (flg1 > 0.0f);
    const bool v2 = (flg2 > 0.0f);

    float sum = 0.0f;
    if (v0) sum += fabsf(gat0 - val0);
    if (v1) sum += fabsf(gat1 - val1);
    if (v2) sum += fabsf(gat2 - val2);

    // person A = segment entries 0..33  (e0 all lanes; e1 lanes 0,1)
    // person B = segment entries 34..67 (e1 lanes 2..31; e2 lanes 0..3)
    const unsigned b0 = __ballot_sync(0xFFFFFFFFu, v0);
    const unsigned b1 = __ballot_sync(0xFFFFFFFFu, v1);
    const unsigned b2 = __ballot_sync(0xFFFFFFFFu, v2);
    const float np = (float)(((b0 | (b1 & 0x3u)) != 0u) +
                             (((b1 & ~0x3u) | b2) != 0u));

    #pragma unroll
    for (int off = 16; off > 0; off >>= 1)
        sum += __shfl_down_sync(0xFFFFFFFFu, sum, off);
    if (lane == 0) s_part[warp] = make_float2(sum, np);
    __syncthreads();

    if (warp == 0) {
        float2 v = s_part[lane];               // 32 warps
        #pragma unroll
        for (int off = 16; off > 0; off >>= 1) {
            v.x += __shfl_down_sync(0xFFFFFFFFu, v.x, off);
            v.y += __shfl_down_sync(0xFFFFFFFFu, v.y, off);
        }
        if (lane == 0)
            out[b] = v.x / v.y;                // reference guarantees np >= 1
    }
}

extern "C" void kernel_launch(void* const* d_in, const int* in_sizes, int n_in,
                              void* d_out, int out_size)
{
    const float* preds = (const float*)d_in[0];
    const float* gts   = (const float*)d_in[1];
    float* out         = (float*)d_out;
    regl1_kernel<<<RB, NTHREADS>>>(preds, gts, out);
}